// round 5
// baseline (speedup 1.0000x reference)
#include <cuda_runtime.h>
#include <cstdint>
#include <cstddef>

// dims fixed by dataset
#define DIM_N 1000
#define DIM_P 100000
#define DIM_B 256
#define GSPLIT 8
#define YSPLIT 20
#define NS_ITERS 8

// -------- device scratch (no allocations allowed) --------
__device__ float g_G    [DIM_N * DIM_N];
__device__ float g_Gpart[GSPLIT * DIM_N * DIM_N];
__device__ float g_Bns  [DIM_N * DIM_N];
__device__ float g_B2ns [DIM_N * DIM_N];
__device__ float g_Tns  [DIM_N * DIM_N];
__device__ float g_Y    [DIM_B * DIM_N];
__device__ float g_Ypart[YSPLIT * DIM_B * DIM_N];
__device__ float g_X    [DIM_B * DIM_N];
__device__ float g_scale[DIM_B];
__device__ float g_cvals[2];   // [0]=||G||_inf (atomicMax), [1]=1/c

// ---------------------------------------------------------------------------
// SIMT fp32 GEMM: 128x128 tile, BK=8, 256 threads, 8x8 per thread,
// double-buffered smem.  BNT=true: B stored [N,K] k-fast -> C=A*B^T.
//                        BNT=false: B stored [K,N] n-fast -> C=A*B.
// EPI 0: C = acc * (scalePtr? scalePtr[0] : 1); split-K partial slot via blockIdx.z
// EPI 1: C = 2*Dptr - acc                      (Newton-Schulz)
// EPI 2: C = scalePtr[row]*acc + clamp(Dptr - acc, +-1e-3)
// ---------------------------------------------------------------------------
#define BM 128
#define BN 128
#define BKK 8
#define TM 8
#define TN 8

template<bool BNT, int EPI>
__global__ void __launch_bounds__(256, 2)
gemm_k(const float* __restrict__ Ag, const float* __restrict__ Bg,
       float* __restrict__ Cg,
       int M, int N, int K, int lda, int ldb, int ldc,
       int kChunk,
       const float* __restrict__ scalePtr,
       const float* __restrict__ Dptr)
{
    __shared__ float As[2][BKK][BM + 4];
    __shared__ float Bs[2][BKK][BN + 4];

    const int tid  = threadIdx.x;
    const int row0 = blockIdx.y * BM;
    const int col0 = blockIdx.x * BN;
    const int kBegin = blockIdx.z * kChunk;
    const int kEnd   = min(K, kBegin + kChunk);
    const int nTiles = (kEnd - kBegin) >> 3;

    // A loader: [M,K] row-major, k-fast
    const int ar = tid >> 1;
    const int ak = (tid & 1) << 2;
    const bool aOk = (row0 + ar) < M;
    const float* aPtr = Ag + (size_t)(row0 + ar) * lda + kBegin + ak;

    // B loader
    int b_r = 0, b_k = 0, b_n = 0;
    const float* bPtr;
    bool bOk = true;
    if (BNT) {
        b_r = tid >> 1; b_k = (tid & 1) << 2;
        bOk = (col0 + b_r) < N;
        bPtr = Bg + (size_t)(col0 + b_r) * ldb + kBegin + b_k;
    } else {
        b_k = tid >> 5;
        b_n = (tid & 31) << 2;
        bPtr = Bg + (size_t)(kBegin + b_k) * ldb + col0 + b_n;
    }

    auto ldgA = [&](int t) -> float4 {
        if (aOk) return *reinterpret_cast<const float4*>(aPtr + (size_t)t * BKK);
        return make_float4(0.f, 0.f, 0.f, 0.f);
    };
    auto ldgB = [&](int t) -> float4 {
        if (BNT) {
            if (bOk) return *reinterpret_cast<const float4*>(bPtr + (size_t)t * BKK);
            return make_float4(0.f, 0.f, 0.f, 0.f);
        } else {
            const float* p = bPtr + (size_t)t * BKK * ldb;
            int c = col0 + b_n;
            if (c + 3 < N) return *reinterpret_cast<const float4*>(p);
            float4 v = make_float4(0.f, 0.f, 0.f, 0.f);
            if (c     < N) v.x = p[0];
            if (c + 1 < N) v.y = p[1];
            if (c + 2 < N) v.z = p[2];
            if (c + 3 < N) v.w = p[3];
            return v;
        }
    };
    auto stsA = [&](int buf, float4 v) {
        As[buf][ak + 0][ar] = v.x; As[buf][ak + 1][ar] = v.y;
        As[buf][ak + 2][ar] = v.z; As[buf][ak + 3][ar] = v.w;
    };
    auto stsB = [&](int buf, float4 v) {
        if (BNT) {
            Bs[buf][b_k + 0][b_r] = v.x; Bs[buf][b_k + 1][b_r] = v.y;
            Bs[buf][b_k + 2][b_r] = v.z; Bs[buf][b_k + 3][b_r] = v.w;
        } else {
            *reinterpret_cast<float4*>(&Bs[buf][b_k][b_n]) = v;
        }
    };

    float acc[TM][TN];
#pragma unroll
    for (int i = 0; i < TM; ++i)
#pragma unroll
        for (int j = 0; j < TN; ++j) acc[i][j] = 0.f;

    const int tx = tid & 15, ty = tid >> 4;
    const int crow = ty * TM, ccol = tx * TN;

    if (nTiles > 0) {
        stsA(0, ldgA(0)); stsB(0, ldgB(0));
        __syncthreads();
        int buf = 0;
        for (int t = 0; t < nTiles; ++t) {
            float4 aNext, bNext;
            const bool more = (t + 1 < nTiles);
            if (more) { aNext = ldgA(t + 1); bNext = ldgB(t + 1); }
#pragma unroll
            for (int kk = 0; kk < BKK; ++kk) {
                float4 a0 = *reinterpret_cast<const float4*>(&As[buf][kk][crow]);
                float4 a1 = *reinterpret_cast<const float4*>(&As[buf][kk][crow + 4]);
                float4 b0 = *reinterpret_cast<const float4*>(&Bs[buf][kk][ccol]);
                float4 b1 = *reinterpret_cast<const float4*>(&Bs[buf][kk][ccol + 4]);
                float a[TM] = {a0.x, a0.y, a0.z, a0.w, a1.x, a1.y, a1.z, a1.w};
                float b[TN] = {b0.x, b0.y, b0.z, b0.w, b1.x, b1.y, b1.z, b1.w};
#pragma unroll
                for (int i = 0; i < TM; ++i)
#pragma unroll
                    for (int j = 0; j < TN; ++j)
                        acc[i][j] = fmaf(a[i], b[j], acc[i][j]);
            }
            if (more) { stsA(buf ^ 1, aNext); stsB(buf ^ 1, bNext); }
            __syncthreads();
            buf ^= 1;
        }
    }

    float* Cw = Cg + (size_t)blockIdx.z * (size_t)M * (size_t)ldc;
    float smul = 1.0f;
    if (EPI == 0 && scalePtr) smul = scalePtr[0];

#pragma unroll
    for (int i = 0; i < TM; ++i) {
        const int r = row0 + crow + i;
        if (r < M) {
            float rowscale = 0.f;
            if (EPI == 2) rowscale = scalePtr[r];
#pragma unroll
            for (int j = 0; j < TN; ++j) {
                const int cc = col0 + ccol + j;
                if (cc < N) {
                    const size_t idx = (size_t)r * ldc + cc;
                    if (EPI == 0) {
                        Cw[idx] = acc[i][j] * smul;
                    } else if (EPI == 1) {
                        Cw[idx] = 2.0f * Dptr[idx] - acc[i][j];
                    } else {
                        float proj = acc[i][j];
                        float rsd  = Dptr[idx] - proj;
                        rsd = fminf(fmaxf(rsd, -1e-3f), 1e-3f);
                        Cw[idx] = fmaf(rowscale, proj, rsd);
                    }
                }
            }
        }
    }
}

// -------- helpers --------
__global__ void reduce_parts(const float* __restrict__ part, float* __restrict__ out,
                             int nElem, int z) {
    int i = blockIdx.x * blockDim.x + threadIdx.x;
    if (i < nElem) {
        float s = 0.f;
        for (int k = 0; k < z; ++k) s += part[(size_t)k * nElem + i];
        out[i] = s;
    }
}

__global__ void zero_cvals(float* cvals) { if (threadIdx.x == 0) cvals[0] = 0.f; }

__global__ void rowabsmax_kernel(const float* __restrict__ G, int n, float* cvals) {
    __shared__ float red[256];
    int r = blockIdx.x;
    float s = 0.f;
    for (int j = threadIdx.x; j < n; j += 256) s += fabsf(G[(size_t)r * n + j]);
    red[threadIdx.x] = s;
    __syncthreads();
    for (int off = 128; off > 0; off >>= 1) {
        if (threadIdx.x < off) red[threadIdx.x] += red[threadIdx.x + off];
        __syncthreads();
    }
    if (threadIdx.x == 0)
        atomicMax(reinterpret_cast<int*>(cvals), __float_as_int(red[0]));
}

__global__ void finalize_c(float* cvals) { if (threadIdx.x == 0) cvals[1] = 1.0f / cvals[0]; }

__global__ void scaleG_kernel(float* G, const float* cvals, int n) {
    int i = blockIdx.x * blockDim.x + threadIdx.x;
    if (i < n) G[i] *= cvals[1];
}

__global__ void init_identity(float* Bm, int n) {
    int i = blockIdx.x * blockDim.x + threadIdx.x;
    if (i < n * n) Bm[i] = ((i / n) == (i % n)) ? 1.0f : 0.0f;
}

__global__ void calc_scale_kernel(const float* __restrict__ Y, const float* __restrict__ X,
                                  float* __restrict__ scale, int Kdim) {
    __shared__ float red[256];
    int b = blockIdx.x;
    float s = 0.f;
    for (int j = threadIdx.x; j < Kdim; j += 256)
        s += Y[(size_t)b * Kdim + j] * X[(size_t)b * Kdim + j];
    red[threadIdx.x] = s;
    __syncthreads();
    for (int off = 128; off > 0; off >>= 1) {
        if (threadIdx.x < off) red[threadIdx.x] += red[threadIdx.x + off];
        __syncthreads();
    }
    if (threadIdx.x == 0) {
        float nrm = sqrtf(fmaxf(red[0], 0.f));
        scale[b] = (nrm > 0.f) ? fminf(1.0f / nrm, 1.0f) : 1.0f;
    }
}

// ---------------------------------------------------------------------------
extern "C" void kernel_launch(void* const* d_in, const int* in_sizes, int n_in,
                              void* d_out, int out_size)
{
    const float* A    = (const float*)d_in[0];   // [1000, 100000]
    const float* priv = (const float*)d_in[1];   // [256, 100000]
    // d_in[2]=L_init, d_in[3]=power_iter: unused (output is basis-invariant)
    float* out = (float*)d_out;

    const int Nn = DIM_N, P = DIM_P, Bb = DIM_B;

    float *G, *Gpart, *Bns, *B2ns, *T, *Yb, *Ypart, *X, *scale, *cvals;
    cudaGetSymbolAddress((void**)&G,     g_G);
    cudaGetSymbolAddress((void**)&Gpart, g_Gpart);
    cudaGetSymbolAddress((void**)&Bns,   g_Bns);
    cudaGetSymbolAddress((void**)&B2ns,  g_B2ns);
    cudaGetSymbolAddress((void**)&T,     g_Tns);
    cudaGetSymbolAddress((void**)&Yb,    g_Y);
    cudaGetSymbolAddress((void**)&Ypart, g_Ypart);
    cudaGetSymbolAddress((void**)&X,     g_X);
    cudaGetSymbolAddress((void**)&scale, g_scale);
    cudaGetSymbolAddress((void**)&cvals, g_cvals);

    // 1) G = A A^T  (split-K=8; 12504 and tail 12472 are both /8)
    {
        dim3 grid(8, 8, GSPLIT);
        gemm_k<true, 0><<<grid, 256>>>(A, A, Gpart, Nn, Nn, P, P, P, Nn,
                                       12504, nullptr, nullptr);
        int nE = Nn * Nn;
        reduce_parts<<<(nE + 255) / 256, 256>>>(Gpart, G, nE, GSPLIT);
    }

    // 2) c = ||G||_inf ; M = G / c (in place)
    zero_cvals<<<1, 32>>>(cvals);
    rowabsmax_kernel<<<Nn, 256>>>(G, Nn, cvals);
    finalize_c<<<1, 32>>>(cvals);
    scaleG_kernel<<<(Nn * Nn + 255) / 256, 256>>>(G, cvals, Nn * Nn);

    // 3) B = M^{-1} via Newton-Schulz:  T = M*B ; B <- 2B - B*T
    init_identity<<<(Nn * Nn + 255) / 256, 256>>>(Bns, Nn);
    {
        float* Bc = Bns;
        float* Bo = B2ns;
        dim3 grid(8, 8, 1);
        for (int it = 0; it < NS_ITERS; ++it) {
            gemm_k<false, 0><<<grid, 256>>>(G, Bc, T, Nn, Nn, Nn, Nn, Nn, Nn,
                                            Nn, nullptr, nullptr);
            gemm_k<false, 1><<<grid, 256>>>(Bc, T, Bo, Nn, Nn, Nn, Nn, Nn, Nn,
                                            Nn, nullptr, Bc);
            float* tmp = Bc; Bc = Bo; Bo = tmp;
        }
        Bns = Bc;  // final inverse of M
    }

    // 4) Y = priv A^T  (split-K=20, chunks of 5000)
    {
        dim3 grid(8, 2, YSPLIT);
        gemm_k<true, 0><<<grid, 256>>>(priv, A, Ypart, Bb, Nn, P, P, P, Nn,
                                       5000, nullptr, nullptr);
        int nE = Bb * Nn;
        reduce_parts<<<(nE + 255) / 256, 256>>>(Ypart, Yb, nE, YSPLIT);
    }

    // 5) X = Y * B * (1/c)  ( = Y G^{-1} )
    {
        dim3 grid(8, 2, 1);
        gemm_k<false, 0><<<grid, 256>>>(Yb, Bns, X, Bb, Nn, Nn, Nn, Nn, Nn,
                                        Nn, cvals + 1, nullptr);
    }

    // 6) scale_b = min(1/||emb_b||, 1), ||emb_b||^2 = <Y_b, X_b>
    calc_scale_kernel<<<Bb, 256>>>(Yb, X, scale, Nn);

    // 7) out = scale[r] * (X A) + clamp(priv - X A, +-1e-3)
    {
        dim3 grid((P + BN - 1) / BN, (Bb + BM - 1) / BM, 1);  // (782, 2)
        gemm_k<false, 2><<<grid, 256>>>(X, A, out, Bb, P, Nn, Nn, P, P,
                                        Nn, scale, priv);
    }
    (void)in_sizes; (void)n_in; (void)out_size;
}